// round 13
// baseline (speedup 1.0000x reference)
#include <cuda_runtime.h>

#define DINL __device__ __forceinline__

namespace {
constexpr int Bn = 32, Sn = 256, En = 256, Hn = 512, Ln = 1024;
constexpr int NBLK = 128, NTHR = 256;
}

__device__ float g_he[Bn * Ln * Hn];        // projected encoder (64 MB)
__device__ float g_hbuf[2][Bn * Hn];
__device__ float g_c[Bn * Hn];
__device__ float g_att[Bn * Hn];
__device__ float g_pm[NBLK], g_ps[NBLK];
__device__ float g_pctx[NBLK * Hn];
__device__ volatile unsigned g_gen;
__device__ unsigned g_cnt;

struct SC { float se[Hn]; float ctx[8][Hn]; float m[8]; float s[8]; };
union SmemU {
    float xs[128][33];   // gate-phase x chunk, [k][b]
    float es[32][132];   // precompute enc chunk, [row][h]
    SC c;
};

DINL void gsync() {
    __threadfence();
    __syncthreads();
    if (threadIdx.x == 0) {
        unsigned target = g_gen + 1u;
        if (atomicAdd(&g_cnt, 1u) == gridDim.x - 1u) {
            g_cnt = 0u;
            __threadfence();
            g_gen = target;
        } else {
            while (g_gen != target) { }
            __threadfence();
        }
    }
    __syncthreads();
}

DINL float wredsum(float v) {
    v += __shfl_xor_sync(0xffffffffu, v, 16);
    v += __shfl_xor_sync(0xffffffffu, v, 8);
    v += __shfl_xor_sync(0xffffffffu, v, 4);
    v += __shfl_xor_sync(0xffffffffu, v, 2);
    v += __shfl_xor_sync(0xffffffffu, v, 1);
    return v;
}

DINL float sigm(float x) { return 1.0f / (1.0f + __expf(-x)); }

DINL float dot4(float4 a, float4 b) {
    return fmaf(a.x, b.x, fmaf(a.y, b.y, fmaf(a.z, b.z, a.w * b.w)));
}
DINL void axpy4(float w, float4 h, float4& c) {
    c.x = fmaf(w, h.x, c.x); c.y = fmaf(w, h.y, c.y);
    c.z = fmaf(w, h.z, c.z); c.w = fmaf(w, h.w, c.w);
}
DINL void scad4(float sc, float4 h, float4& c) {   // c = c*sc + h
    c.x = fmaf(c.x, sc, h.x); c.y = fmaf(c.y, sc, h.y);
    c.z = fmaf(c.z, sc, h.z); c.w = fmaf(c.w, sc, h.w);
}

__global__ void __launch_bounds__(NTHR, 1) aas_kernel(
    const float* __restrict__ y,    const float* __restrict__ enc,
    const float* __restrict__ W_ih, const float* __restrict__ b_ih,
    const float* __restrict__ W_hh, const float* __restrict__ b_hh,
    const float* __restrict__ W_s,  const float* __restrict__ b_s,
    const float* __restrict__ W_h,  const float* __restrict__ b_h,
    float* __restrict__ outp)
{
    __shared__ SmemU smu;
    __shared__ float sm_g[4][4][32];

    const int tid  = threadIdx.x;
    const int lane = tid & 31;
    const int w    = tid >> 5;
    const int bid  = blockIdx.x;
    const int gtid = bid * NTHR + tid;

    // ---------------- init state ----------------
    for (int i = gtid; i < Bn * Hn; i += NBLK * NTHR) {
        g_hbuf[0][i] = 0.f; g_hbuf[1][i] = 0.f; g_c[i] = 0.f;
        __stcg(&g_att[i], 0.f);
    }

    // ---------------- precompute h_e = enc @ W_h^T + b_h ----------------
    // block handles row-groups of 32; warp w owns output cols [w*64, w*64+64)
    for (int rg = bid; rg < (Bn * Ln) / 32; rg += NBLK) {
        float acc[64];
#pragma unroll
        for (int kk = 0; kk < 64; kk++) acc[kk] = 0.f;
        const int kbase = w * 64;
        for (int ch = 0; ch < 4; ch++) {
            __syncthreads();
            {   // stage enc rows [rg*32 .. +32), h in [ch*128, +128)
                const int b = tid & 31, kg = tid >> 5;
                const float* src = enc + (rg * 32 + b) * Hn + ch * 128 + kg * 16;
#pragma unroll
                for (int i = 0; i < 4; i++) {
                    float4 v = *(const float4*)(src + i * 4);
                    const int k = kg * 16 + i * 4;
                    smu.es[b][k] = v.x; smu.es[b][k + 1] = v.y;
                    smu.es[b][k + 2] = v.z; smu.es[b][k + 3] = v.w;
                }
            }
            __syncthreads();
            for (int h4 = 0; h4 < 128; h4 += 4) {
                const float4 x = *(const float4*)&smu.es[lane][h4];
                const float* wp = W_h + kbase * Hn + ch * 128 + h4;
#pragma unroll
                for (int kk = 0; kk < 64; kk++) {
                    const float4 wv = *(const float4*)(wp + kk * Hn);
                    acc[kk] = fmaf(wv.x, x.x, fmaf(wv.y, x.y,
                              fmaf(wv.z, x.z, fmaf(wv.w, x.w, acc[kk]))));
                }
            }
        }
        float* dst = g_he + (rg * 32 + lane) * Hn + kbase;
#pragma unroll
        for (int kk = 0; kk < 64; kk++) dst[kk] = acc[kk] + b_h[kbase + kk];
    }
    gsync();

    // ==================== time-step loop ====================
#pragma unroll 1
    for (int ts = 0; ts < Sn; ts++) {
        const int cur = ts & 1, nxt = cur ^ 1;

        // ---------- A: gates + LSTM cell ----------
        {
            float acc0 = 0.f, acc1 = 0.f;
            const int q = w >> 1;
            const int rloc = (w & 1) * 2;
            const int r0 = q * Hn + bid * 4 + rloc;
#pragma unroll 1
            for (int ch = 0; ch < 10; ch++) {
                __syncthreads();
                {   // stage x chunk [k][b]
                    const int b = tid & 31, kg = tid >> 5;
                    const float* src;
                    if (ch < 2)      src = y + (b * Sn + ts) * En + ch * 128;
                    else if (ch < 6) src = g_att + b * Hn + (ch - 2) * 128;
                    else             src = g_hbuf[cur] + b * Hn + (ch - 6) * 128;
                    src += kg * 16;
#pragma unroll
                    for (int i = 0; i < 4; i++) {
                        float4 v = (ch < 2) ? *(const float4*)(src + i * 4)
                                            : __ldcg((const float4*)(src + i * 4));
                        const int k = kg * 16 + i * 4;
                        smu.xs[k][b] = v.x; smu.xs[k + 1][b] = v.y;
                        smu.xs[k + 2][b] = v.z; smu.xs[k + 3][b] = v.w;
                    }
                }
                __syncthreads();
                const float* w0p = (ch < 6) ? W_ih + r0 * 768 + ch * 128
                                            : W_hh + r0 * Hn + (ch - 6) * 128;
                const float* w1p = w0p + ((ch < 6) ? 768 : Hn);
#pragma unroll 8
                for (int g4 = 0; g4 < 32; g4++) {
                    const int kk = g4 * 4;
                    const float4 wa = *(const float4*)(w0p + kk);
                    const float4 wb = *(const float4*)(w1p + kk);
                    const float x0 = smu.xs[kk][lane], x1 = smu.xs[kk + 1][lane];
                    const float x2 = smu.xs[kk + 2][lane], x3 = smu.xs[kk + 3][lane];
                    acc0 = fmaf(wa.x, x0, fmaf(wa.y, x1, fmaf(wa.z, x2, fmaf(wa.w, x3, acc0))));
                    acc1 = fmaf(wb.x, x0, fmaf(wb.y, x1, fmaf(wb.z, x2, fmaf(wb.w, x3, acc1))));
                }
            }
            __syncthreads();
            sm_g[q][rloc][lane]     = acc0 + b_ih[r0] + b_hh[r0];
            sm_g[q][rloc + 1][lane] = acc1 + b_ih[r0 + 1] + b_hh[r0 + 1];
            __syncthreads();
            if (tid < 128) {
                const int j = tid >> 5, b = tid & 31, u = bid * 4 + j;
                const float ig = sigm(sm_g[0][j][b]);
                const float fg = sigm(sm_g[1][j][b]);
                const float gg = tanhf(sm_g[2][j][b]);
                const float og = sigm(sm_g[3][j][b]);
                const float c = fmaf(fg, g_c[b * Hn + u], ig * gg);
                g_c[b * Hn + u] = c;
                const float h = og * tanhf(c);
                __stcg(&g_hbuf[nxt][b * Hn + u], h);
                outp[(b * Sn + ts) * Hn + u] = h;
            }
        }
        gsync();

        // ---------- C: s_e + fused attention (online softmax) ----------
        {
            const int b = bid >> 2, chunk = bid & 3;
            const float* hb = g_hbuf[nxt] + b * Hn;
            // s_e[b][m] for m in [w*64, w*64+64), 4 concurrent reductions
            for (int mi = 0; mi < 64; mi += 4) {
                float p0 = 0.f, p1 = 0.f, p2 = 0.f, p3 = 0.f;
                const float* wsp = W_s + (w * 64 + mi) * Hn;
#pragma unroll
                for (int i = 0; i < 4; i++) {
                    const int k4 = (i * 32 + lane) * 4;
                    const float4 hv = __ldcg((const float4*)(hb + k4));
                    p0 = fmaf(1.f, dot4(*(const float4*)(wsp + k4), hv), p0);
                    p1 = fmaf(1.f, dot4(*(const float4*)(wsp + Hn + k4), hv), p1);
                    p2 = fmaf(1.f, dot4(*(const float4*)(wsp + 2 * Hn + k4), hv), p2);
                    p3 = fmaf(1.f, dot4(*(const float4*)(wsp + 3 * Hn + k4), hv), p3);
                }
                p0 = wredsum(p0); p1 = wredsum(p1);
                p2 = wredsum(p2); p3 = wredsum(p3);
                if (lane == 0) {
                    const int m = w * 64 + mi;
                    smu.c.se[m]     = p0 + b_s[m];
                    smu.c.se[m + 1] = p1 + b_s[m + 1];
                    smu.c.se[m + 2] = p2 + b_s[m + 2];
                    smu.c.se[m + 3] = p3 + b_s[m + 3];
                }
            }
            __syncthreads();

            float4 se4[4];
#pragma unroll
            for (int i = 0; i < 4; i++)
                se4[i] = *(const float4*)&smu.c.se[i * 128 + lane * 4];

            float mloc = -1e30f, sloc = 0.f;
            float4 c0 = {0,0,0,0}, c1 = c0, c2 = c0, c3 = c0;
            const float* hebase = g_he + (b * Ln + chunk * 256 + w * 32) * Hn;
#pragma unroll 1
            for (int li = 0; li < 32; li++) {
                const float* hp = hebase + li * Hn + lane * 4;
                const float4 h0 = *(const float4*)(hp);
                const float4 h1 = *(const float4*)(hp + 128);
                const float4 h2 = *(const float4*)(hp + 256);
                const float4 h3 = *(const float4*)(hp + 384);
                float e = dot4(se4[0], h0) + dot4(se4[1], h1)
                        + dot4(se4[2], h2) + dot4(se4[3], h3);
                e = wredsum(e);
                if (e <= mloc) {
                    const float wgt = __expf(e - mloc);
                    sloc += wgt;
                    axpy4(wgt, h0, c0); axpy4(wgt, h1, c1);
                    axpy4(wgt, h2, c2); axpy4(wgt, h3, c3);
                } else {
                    const float sc = __expf(mloc - e);
                    sloc = fmaf(sloc, sc, 1.f);
                    scad4(sc, h0, c0); scad4(sc, h1, c1);
                    scad4(sc, h2, c2); scad4(sc, h3, c3);
                    mloc = e;
                }
            }
            if (lane == 0) { smu.c.m[w] = mloc; smu.c.s[w] = sloc; }
            *(float4*)&smu.c.ctx[w][lane * 4]       = c0;
            *(float4*)&smu.c.ctx[w][128 + lane * 4] = c1;
            *(float4*)&smu.c.ctx[w][256 + lane * 4] = c2;
            *(float4*)&smu.c.ctx[w][384 + lane * 4] = c3;
            __syncthreads();
            {
                float M = smu.c.m[0];
#pragma unroll
                for (int w2 = 1; w2 < 8; w2++) M = fmaxf(M, smu.c.m[w2]);
                float wsc[8]; float Sb = 0.f;
#pragma unroll
                for (int w2 = 0; w2 < 8; w2++) {
                    wsc[w2] = __expf(smu.c.m[w2] - M);
                    Sb = fmaf(wsc[w2], smu.c.s[w2], Sb);
                }
#pragma unroll
                for (int r = 0; r < 2; r++) {
                    const int h = tid + r * 256;
                    float v = 0.f;
#pragma unroll
                    for (int w2 = 0; w2 < 8; w2++)
                        v = fmaf(wsc[w2], smu.c.ctx[w2][h], v);
                    __stcg(&g_pctx[bid * Hn + h], v);
                }
                if (tid == 0) { __stcg(&g_pm[bid], M); __stcg(&g_ps[bid], Sb); }
            }
        }
        gsync();

        // ---------- D: combine 4 chunk-partials -> att ----------
        if (gtid < Bn * Hn) {
            const int b = gtid >> 9, h = gtid & 511;
            float pm[4], M;
#pragma unroll
            for (int cc = 0; cc < 4; cc++) pm[cc] = __ldcg(&g_pm[b * 4 + cc]);
            M = fmaxf(fmaxf(pm[0], pm[1]), fmaxf(pm[2], pm[3]));
            float Sd = 0.f, v = 0.f;
#pragma unroll
            for (int cc = 0; cc < 4; cc++) {
                const float wsc = __expf(pm[cc] - M);
                Sd = fmaf(wsc, __ldcg(&g_ps[b * 4 + cc]), Sd);
                v  = fmaf(wsc, __ldcg(&g_pctx[(b * 4 + cc) * Hn + h]), v);
            }
            const float a = v / Sd;
            __stcg(&g_att[b * Hn + h], a);
            outp[Bn * Sn * Hn + (b * Sn + ts) * Hn + h] = a;
        }
        gsync();
    }
}

extern "C" void kernel_launch(void* const* d_in, const int* in_sizes, int n_in,
                              void* d_out, int out_size) {
    (void)in_sizes; (void)n_in; (void)out_size;
    aas_kernel<<<NBLK, NTHR>>>(
        (const float*)d_in[0], (const float*)d_in[1],
        (const float*)d_in[2], (const float*)d_in[3],
        (const float*)d_in[4], (const float*)d_in[5],
        (const float*)d_in[6], (const float*)d_in[7],
        (const float*)d_in[8], (const float*)d_in[9],
        (float*)d_out);
}